// round 9
// baseline (speedup 1.0000x reference)
#include <cuda_runtime.h>
#include <math.h>

#define NQ   1001
#define KK   5
#define MM   50
#define DK   64
#define DV   128
#define DS   50
#define BB   128
#define SS   2048

#define NBT      (BB*SS)
#define OFF_ALPHA  (NBT)
#define OFF_BETA   (2*NBT)
#define OFF_LOGITS (2*NBT + NBT*4)
#define OFF_PROBS  (2*NBT + NBT*4 + NBT*5)

typedef unsigned long long u64;

__device__ __forceinline__ u64 fma2(u64 a, u64 b, u64 c) {
    u64 d;
    asm("fma.rn.f32x2 %0, %1, %2, %3;" : "=l"(d) : "l"(a), "l"(b), "l"(c));
    return d;
}
__device__ __forceinline__ u64 pack2(float x, float y) {
    u64 d;
    asm("mov.b64 %0, {%1, %2};" : "=l"(d) : "r"(__float_as_uint(x)), "r"(__float_as_uint(y)));
    return d;
}
__device__ __forceinline__ float2 unpack2(u64 v) {
    float2 f;
    asm("mov.b64 {%0, %1}, %2;" : "=f"(f.x), "=f"(f.y) : "l"(v));
    return f;
}

// ---------------- static scratch ----------------
__device__ float g_W1e[69*DV];
__device__ float g_b1e[DV];
__device__ float g_W1a[69*DV];
__device__ float g_b1a[DV];
__device__ __align__(16) u64 g_attn2[NQ*64];      // dup-packed, padded to 64 m-slots
__device__ __align__(16) u64 g_ea[NQ*KK*128];     // per vp: [2*vp]=(-e0,-e1) [2*vp+1]=(a0,a1)
__device__ float g_sumq_tab[NQ*DS];               // q_e @ summary_w[128:192,:] + summary_b
__device__ float g_alpha_tab[NQ];
__device__ float g_beta_tab[NQ*4];
__device__ float g_read[(size_t)NBT*DV];

// ---------------- K0: fuse value_proj through erase/add ----------
__global__ void fuse_kernel(const float* __restrict__ vp_w, const float* __restrict__ vp_b,
                            const float* __restrict__ er_w, const float* __restrict__ er_b,
                            const float* __restrict__ ad_w, const float* __restrict__ ad_b)
{
    int j = threadIdx.x;
    int row = blockIdx.x;
    if (row < 69) {
        float ae = 0.f, aa = 0.f;
        #pragma unroll 8
        for (int k = 0; k < DV; k++) {
            float w = vp_w[row*DV + k];
            ae = fmaf(w, er_w[k*DV + j], ae);
            aa = fmaf(w, ad_w[k*DV + j], aa);
        }
        g_W1e[row*DV + j] = ae;
        g_W1a[row*DV + j] = aa;
    } else {
        float be = er_b[j], ba = ad_b[j];
        #pragma unroll 8
        for (int k = 0; k < DV; k++) {
            float b = vp_b[k];
            be = fmaf(b, er_w[k*DV + j], be);
            ba = fmaf(b, ad_w[k*DV + j], ba);
        }
        g_b1e[j] = be;
        g_b1a[j] = ba;
    }
}

// ---------------- K1: per-question tables ----------------
__global__ void qtab_kernel(const float* __restrict__ q_embed_w,
                            const float* __restrict__ key_mem,
                            const float* __restrict__ summary_w,
                            const float* __restrict__ summary_b,
                            const float* __restrict__ alpha_w, const float* __restrict__ alpha_b,
                            const float* __restrict__ beta_w,  const float* __restrict__ beta_b)
{
    int q = blockIdx.x;
    int tid = threadIdx.x;               // 64 threads
    __shared__ float qe[DK];
    __shared__ float lg[MM];
    __shared__ float aw[64];
    qe[tid] = q_embed_w[q*DK + tid];
    __syncthreads();

    if (tid < MM) {
        float acc = 0.f;
        #pragma unroll 8
        for (int i = 0; i < DK; i++) acc = fmaf(qe[i], key_mem[tid*DK + i], acc);
        lg[tid] = acc;
    }
    __syncthreads();
    if (tid == 0) {
        float mx = lg[0];
        for (int m = 1; m < MM; m++) mx = fmaxf(mx, lg[m]);
        float s = 0.f;
        for (int m = 0; m < MM; m++) { float e = expf(lg[m] - mx); aw[m] = e; s += e; }
        float inv = 1.f / s;
        for (int m = 0; m < MM; m++) aw[m] *= inv;
        for (int m = MM; m < 64; m++) aw[m] = 0.f;
    }
    __syncthreads();
    {
        float v = aw[tid];
        g_attn2[q*64 + tid] = pack2(v, v);
    }

    if (tid < DS) {
        float acc = summary_b[tid];
        #pragma unroll 8
        for (int i = 0; i < DK; i++)
            acc = fmaf(qe[i], summary_w[(DV + i)*DS + tid], acc);
        g_sumq_tab[q*DS + tid] = acc;
    }
    if (tid == 0) {
        float d = alpha_b[0];
        for (int i = 0; i < DK; i++) d = fmaf(qe[i], alpha_w[i], d);
        g_alpha_tab[q] = (d > 20.f) ? d : log1pf(expf(d));
    }
    if (tid < 4) {
        float d = beta_b[tid];
        for (int i = 0; i < DK; i++) d = fmaf(qe[i], beta_w[i*4 + tid], d);
        g_beta_tab[q*4 + tid] = d;
    }
}

// ---------------- K2: per-(q,r) erase/add table, packed ----------------
__global__ void ertab_kernel(const float* __restrict__ item_embed_w)
{
    int q = blockIdx.x / KK;
    int r = blockIdx.x % KK;
    int j = threadIdx.x;                 // 128 threads
    __shared__ float it[DK];
    __shared__ float es[DV];
    __shared__ float as_[DV];
    if (j < DK) it[j] = item_embed_w[q*DK + j];
    __syncthreads();

    float rf[KK];
    #pragma unroll
    for (int k = 0; k < KK; k++) {
        float d = fabsf((float)k - (float)r) * 0.25f;
        rf[k] = fmaxf(1.f - d, 0.f);
    }
    float pe = g_b1e[j], pa = g_b1a[j];
    #pragma unroll 8
    for (int i = 0; i < DK; i++) {
        float x = it[i];
        pe = fmaf(x, g_W1e[i*DV + j], pe);
        pa = fmaf(x, g_W1a[i*DV + j], pa);
    }
    #pragma unroll
    for (int k = 0; k < KK; k++) {
        pe = fmaf(rf[k], g_W1e[(DK + k)*DV + j], pe);
        pa = fmaf(rf[k], g_W1a[(DK + k)*DV + j], pa);
    }
    es[j]  = 1.f / (1.f + expf(-pe));
    as_[j] = tanhf(pa);
    __syncthreads();

    if (j < 64) {
        int c = q*KK + r;
        g_ea[(size_t)c*128 + j*2]     = pack2(-es[2*j], -es[2*j+1]);
        g_ea[(size_t)c*128 + j*2 + 1] = pack2(as_[2*j], as_[2*j+1]);
    }
}

// ---------------- K3: scan — 1024 blocks x 64 thr, 8-way m-split ----------
// grid = 1024 = 128 batches x 8 v-slices; block = 64 thr (2 warps).
// tid = mh*8 + vpl; thread owns mem rows m = mh*7 .. mh*7+6 for v-pair vp.
// attn (56 u64) and ea (8 ulonglong2) staged per block-step into smem by
// designated threads; double-buffered, ONE __syncthreads per step, depth-2
// LDG prefetch so the STS never waits on an in-flight global load.
__global__ void __launch_bounds__(64, 8)
scan_kernel(const int* __restrict__ questions, const int* __restrict__ responses,
            const float* __restrict__ init_mem)
{
    const int tid = threadIdx.x;
    const int vpl = tid & 7;
    const int mh  = tid >> 3;                 // 0..7
    const int b   = blockIdx.x >> 3;
    const int vs  = blockIdx.x & 7;
    const int vp  = vs*8 + vpl;               // 0..63

    __shared__ __align__(16) u64 s_attn[2][64];        // 8 groups of 8 (7 used)
    __shared__ __align__(16) ulonglong2 s_ea[2][8];    // per vpl: (ne, a)
    __shared__ __align__(16) u64 s_rd[2][8][8];        // [vpl][mh] partials

    u64 mem[7];
    #pragma unroll
    for (int j = 0; j < 7; j++) {
        int m = mh*7 + j;
        if (m < MM) {
            float2 iv = *(const float2*)(init_mem + m*DV + 2*vp);
            mem[j] = pack2(iv.x, iv.y);
        } else mem[j] = 0ULL;
    }

    const int base = b*SS;

    int q0 = questions[base + 0], r0 = responses[base + 0];
    int q1 = questions[base + 1], r1 = responses[base + 1];
    int q2 = questions[base + 2], r2 = responses[base + 2];

    // attn slot remap: m = g*7+i -> slot g*8+i (aligned vector LDS reads)
    const int g_   = tid / 7;
    const int slot = g_*8 + (tid - g_*7);

    // stage t=0 into buf0; hold t=1 in regs; indices for t=2 in q2/r2
    u64 ap_n1 = 0ULL;
    ulonglong2 ea_n1 = make_ulonglong2(0ULL, 0ULL);
    if (tid < 56) {
        s_attn[0][slot] = g_attn2[q0*64 + tid];
        ap_n1 = g_attn2[q1*64 + tid];
    }
    if (tid < 8) {
        s_ea[0][tid] = *(const ulonglong2*)(g_ea + ((size_t)(q0*KK + r0))*128 + (vs*8 + tid)*2);
        ea_n1        = *(const ulonglong2*)(g_ea + ((size_t)(q1*KK + r1))*128 + (vs*8 + tid)*2);
    }
    __syncthreads();

    float* rdout = g_read + (size_t)base*DV + 2*vp;

    for (int t = 0; t < SS; t++) {
        // depth-2 prefetch: tables for t+2, indices for t+3
        u64 ap_n2 = 0ULL;
        ulonglong2 ea_n2 = make_ulonglong2(0ULL, 0ULL);
        if (tid < 56) ap_n2 = g_attn2[q2*64 + tid];
        if (tid < 8)
            ea_n2 = *(const ulonglong2*)(g_ea + ((size_t)(q2*KK + r2))*128 + (vs*8 + tid)*2);
        int tn = (t + 3 < SS) ? (t + 3) : (SS - 1);
        int q3 = questions[base + tn], r3 = responses[base + tn];

        // stage tables for t+1 (registers landed a full iteration ago)
        if (tid < 56) s_attn[(t + 1) & 1][slot] = ap_n1;
        if (tid < 8)  s_ea[(t + 1) & 1][tid] = ea_n1;

        // body: 7 m-rows x 3 packed FMAs; attn + ea via broadcast LDS
        const int buf = t & 1;
        const ulonglong2 E = s_ea[buf][vpl];
        const u64 ne = E.x, ad = E.y;
        const u64* at = &s_attn[buf][mh*8];
        u64 rd = 0ULL;
        #pragma unroll
        for (int jj = 0; jj < 3; jj++) {
            ulonglong2 T = *(const ulonglong2*)(at + 2*jj);
            u64 m0 = mem[2*jj], m1 = mem[2*jj + 1];
            rd = fma2(T.x, m0, rd);
            u64 t0 = fma2(ne, m0, ad);
            mem[2*jj] = fma2(T.x, t0, m0);
            rd = fma2(T.y, m1, rd);
            u64 t1 = fma2(ne, m1, ad);
            mem[2*jj + 1] = fma2(T.y, t1, m1);
        }
        {
            u64 T = at[6];
            rd = fma2(T, mem[6], rd);
            u64 t0 = fma2(ne, mem[6], ad);
            mem[6] = fma2(T, t0, mem[6]);
        }

        s_rd[buf][vpl][mh] = rd;
        __syncthreads();

        if (mh == 0) {
            const ulonglong2* p = (const ulonglong2*)(&s_rd[buf][vpl][0]);
            ulonglong2 a0 = p[0], a1 = p[1], a2 = p[2], a3 = p[3];
            float2 f0 = unpack2(a0.x), f1 = unpack2(a0.y);
            float2 f2 = unpack2(a1.x), f3 = unpack2(a1.y);
            float2 f4 = unpack2(a2.x), f5 = unpack2(a2.y);
            float2 f6 = unpack2(a3.x), f7 = unpack2(a3.y);
            float2 o;
            o.x = ((f0.x + f1.x) + (f2.x + f3.x)) + ((f4.x + f5.x) + (f6.x + f7.x));
            o.y = ((f0.y + f1.y) + (f2.y + f3.y)) + ((f4.y + f5.y) + (f6.y + f7.y));
            *(float2*)(rdout + (size_t)t*DV) = o;
        }

        ap_n1 = ap_n2;
        ea_n1 = ea_n2;
        q2 = q3; r2 = r3;
    }
}

// ---------------- K4: epilogue — w in regs, 8-row barrier groups -----------
#define TB 32
#define RT 8
__global__ void __launch_bounds__(128)
out_kernel(const int* __restrict__ questions,
           const float* __restrict__ summary_w,
           const float* __restrict__ theta_w,
           const float* __restrict__ theta_b,
           float* __restrict__ out)
{
    const int tid  = threadIdx.x;
    const int s    = tid & 63;
    const int ih   = tid >> 6;
    const int lane = tid & 31;
    const int wid  = tid >> 5;

    __shared__ float s_read[RT][DV];
    __shared__ float s_part[RT][64];
    __shared__ float s_sum[RT][52];
    __shared__ int   s_q[RT];

    const int sc = (s < DS) ? s : 0;
    float w[64];
    #pragma unroll
    for (int j = 0; j < 64; j++)
        w[j] = summary_w[(ih*64 + j)*DS + sc];

    float tw0 = 0.f, tw1 = 0.f;
    if (lane < 25) { tw0 = theta_w[2*lane]; tw1 = theta_w[2*lane + 1]; }
    const float tb0 = theta_b[0];

    #pragma unroll 1
    for (int tile = 0; tile < TB/RT; tile++) {
        const int bt0 = blockIdx.x * TB + tile * RT;

        if (tid < RT) s_q[tid] = questions[bt0 + tid];
        {
            float4* dst = (float4*)&s_read[0][0];
            const float4* src = (const float4*)(g_read + (size_t)bt0*DV);
            dst[tid]       = src[tid];
            dst[tid + 128] = src[tid + 128];
        }
        __syncthreads();

        float sumq[RT];
        if (!ih && s < DS) {
            #pragma unroll
            for (int r = 0; r < RT; r++) sumq[r] = g_sumq_tab[s_q[r]*DS + s];
        }

        float acc[RT];
        #pragma unroll
        for (int r = 0; r < RT; r++) {
            float a = 0.f;
            const float4* r4 = (const float4*)(&s_read[r][ih*64]);
            #pragma unroll
            for (int j = 0; j < 16; j++) {
                float4 rv = r4[j];
                a = fmaf(rv.x, w[4*j+0], a);
                a = fmaf(rv.y, w[4*j+1], a);
                a = fmaf(rv.z, w[4*j+2], a);
                a = fmaf(rv.w, w[4*j+3], a);
            }
            acc[r] = a;
        }
        if (ih) {
            #pragma unroll
            for (int r = 0; r < RT; r++) s_part[r][s] = acc[r];
        }
        __syncthreads();

        if (!ih && s < DS) {
            #pragma unroll
            for (int r = 0; r < RT; r++)
                s_sum[r][s] = tanhf(acc[r] + s_part[r][s] + sumq[r]);
        }
        __syncthreads();

        #pragma unroll
        for (int k = 0; k < 2; k++) {
            const int r  = wid*2 + k;
            const int bt = bt0 + r;
            const int q  = s_q[r];
            float p = (lane < 25) ? s_sum[r][2*lane]*tw0 + s_sum[r][2*lane+1]*tw1 : 0.f;
            p += __shfl_xor_sync(0xffffffffu, p, 16);
            p += __shfl_xor_sync(0xffffffffu, p, 8);
            p += __shfl_xor_sync(0xffffffffu, p, 4);
            p += __shfl_xor_sync(0xffffffffu, p, 2);
            p += __shfl_xor_sync(0xffffffffu, p, 1);
            if (lane == 0) {
                float th = tanhf(p + tb0);
                float al = g_alpha_tab[q];
                float inter = th * al;

                float l[5];
                l[0] = 0.f;
                #pragma unroll
                for (int cc = 0; cc < 4; cc++)
                    l[cc+1] = l[cc] + (inter - g_beta_tab[q*4 + cc]);

                float mx = l[0];
                #pragma unroll
                for (int cc = 1; cc < 5; cc++) mx = fmaxf(mx, l[cc]);
                float ex[5], sm = 0.f;
                #pragma unroll
                for (int cc = 0; cc < 5; cc++) { ex[cc] = __expf(l[cc] - mx); sm += ex[cc]; }
                float inv = 1.f / sm;

                out[bt]             = th;
                out[OFF_ALPHA + bt] = al;
                #pragma unroll
                for (int cc = 0; cc < 4; cc++) out[OFF_BETA + bt*4 + cc] = g_beta_tab[q*4 + cc];
                #pragma unroll
                for (int cc = 0; cc < 5; cc++) out[OFF_LOGITS + bt*5 + cc] = l[cc];
                #pragma unroll
                for (int cc = 0; cc < 5; cc++) out[OFF_PROBS  + bt*5 + cc] = ex[cc] * inv;
            }
        }
        __syncthreads();
    }
}

// ---------------- launch ----------------
extern "C" void kernel_launch(void* const* d_in, const int* in_sizes, int n_in,
                              void* d_out, int out_size)
{
    const int*   questions    = (const int*)  d_in[0];
    const int*   responses    = (const int*)  d_in[1];
    const float* q_embed_w    = (const float*)d_in[2];
    const float* item_embed_w = (const float*)d_in[3];
    const float* value_proj_w = (const float*)d_in[4];
    const float* value_proj_b = (const float*)d_in[5];
    const float* key_mem      = (const float*)d_in[6];
    const float* init_mem     = (const float*)d_in[7];
    const float* erase_w      = (const float*)d_in[8];
    const float* erase_b      = (const float*)d_in[9];
    const float* add_w        = (const float*)d_in[10];
    const float* add_b        = (const float*)d_in[11];
    const float* summary_w    = (const float*)d_in[12];
    const float* summary_b    = (const float*)d_in[13];
    const float* theta_w      = (const float*)d_in[14];
    const float* theta_b      = (const float*)d_in[15];
    const float* alpha_w      = (const float*)d_in[16];
    const float* alpha_b      = (const float*)d_in[17];
    const float* beta_w       = (const float*)d_in[18];
    const float* beta_b       = (const float*)d_in[19];
    float* out = (float*)d_out;

    fuse_kernel <<<70, DV>>>(value_proj_w, value_proj_b, erase_w, erase_b, add_w, add_b);
    qtab_kernel <<<NQ, 64>>>(q_embed_w, key_mem, summary_w, summary_b,
                             alpha_w, alpha_b, beta_w, beta_b);
    ertab_kernel<<<NQ*KK, DV>>>(item_embed_w);
    scan_kernel <<<BB*8, 64>>>(questions, responses, init_mem);
    out_kernel  <<<NBT/TB, 128>>>(questions, summary_w, theta_w, theta_b, out);
}

// round 11
// speedup vs baseline: 1.2437x; 1.2437x over previous
#include <cuda_runtime.h>
#include <math.h>

#define NQ   1001
#define KK   5
#define MM   50
#define DK   64
#define DV   128
#define DS   50
#define BB   128
#define SS   2048

#define NBT      (BB*SS)
#define OFF_ALPHA  (NBT)
#define OFF_BETA   (2*NBT)
#define OFF_LOGITS (2*NBT + NBT*4)
#define OFF_PROBS  (2*NBT + NBT*4 + NBT*5)

typedef unsigned long long u64;

__device__ __forceinline__ u64 fma2(u64 a, u64 b, u64 c) {
    u64 d;
    asm("fma.rn.f32x2 %0, %1, %2, %3;" : "=l"(d) : "l"(a), "l"(b), "l"(c));
    return d;
}
__device__ __forceinline__ u64 pack2(float x, float y) {
    u64 d;
    asm("mov.b64 %0, {%1, %2};" : "=l"(d) : "r"(__float_as_uint(x)), "r"(__float_as_uint(y)));
    return d;
}
__device__ __forceinline__ float2 unpack2(u64 v) {
    float2 f;
    asm("mov.b64 {%0, %1}, %2;" : "=f"(f.x), "=f"(f.y) : "l"(v));
    return f;
}

// ---------------- static scratch ----------------
__device__ float g_W1e[69*DV];
__device__ float g_b1e[DV];
__device__ float g_W1a[69*DV];
__device__ float g_b1a[DV];
__device__ __align__(16) u64 g_attn2[NQ*64];      // dup-packed, padded to 64 m-slots
__device__ __align__(16) u64 g_ea[NQ*KK*128];     // per vp: [2*vp]=(-e0,-e1) [2*vp+1]=(a0,a1)
__device__ float g_sumq_tab[NQ*DS];               // q_e @ summary_w[128:192,:] + summary_b
__device__ float g_alpha_tab[NQ];
__device__ float g_beta_tab[NQ*4];
__device__ float g_read[(size_t)NBT*DV];

// ---------------- K0: fuse value_proj through erase/add ----------
__global__ void fuse_kernel(const float* __restrict__ vp_w, const float* __restrict__ vp_b,
                            const float* __restrict__ er_w, const float* __restrict__ er_b,
                            const float* __restrict__ ad_w, const float* __restrict__ ad_b)
{
    int j = threadIdx.x;
    int row = blockIdx.x;
    if (row < 69) {
        float ae = 0.f, aa = 0.f;
        #pragma unroll 8
        for (int k = 0; k < DV; k++) {
            float w = vp_w[row*DV + k];
            ae = fmaf(w, er_w[k*DV + j], ae);
            aa = fmaf(w, ad_w[k*DV + j], aa);
        }
        g_W1e[row*DV + j] = ae;
        g_W1a[row*DV + j] = aa;
    } else {
        float be = er_b[j], ba = ad_b[j];
        #pragma unroll 8
        for (int k = 0; k < DV; k++) {
            float b = vp_b[k];
            be = fmaf(b, er_w[k*DV + j], be);
            ba = fmaf(b, ad_w[k*DV + j], ba);
        }
        g_b1e[j] = be;
        g_b1a[j] = ba;
    }
}

// ---------------- K1: per-question tables ----------------
__global__ void qtab_kernel(const float* __restrict__ q_embed_w,
                            const float* __restrict__ key_mem,
                            const float* __restrict__ summary_w,
                            const float* __restrict__ summary_b,
                            const float* __restrict__ alpha_w, const float* __restrict__ alpha_b,
                            const float* __restrict__ beta_w,  const float* __restrict__ beta_b)
{
    int q = blockIdx.x;
    int tid = threadIdx.x;               // 64 threads
    __shared__ float qe[DK];
    __shared__ float lg[MM];
    __shared__ float aw[64];
    qe[tid] = q_embed_w[q*DK + tid];
    __syncthreads();

    if (tid < MM) {
        float acc = 0.f;
        #pragma unroll 8
        for (int i = 0; i < DK; i++) acc = fmaf(qe[i], key_mem[tid*DK + i], acc);
        lg[tid] = acc;
    }
    __syncthreads();
    if (tid == 0) {
        float mx = lg[0];
        for (int m = 1; m < MM; m++) mx = fmaxf(mx, lg[m]);
        float s = 0.f;
        for (int m = 0; m < MM; m++) { float e = expf(lg[m] - mx); aw[m] = e; s += e; }
        float inv = 1.f / s;
        for (int m = 0; m < MM; m++) aw[m] *= inv;
        for (int m = MM; m < 64; m++) aw[m] = 0.f;
    }
    __syncthreads();
    {
        float v = aw[tid];
        g_attn2[q*64 + tid] = pack2(v, v);
    }

    if (tid < DS) {
        float acc = summary_b[tid];
        #pragma unroll 8
        for (int i = 0; i < DK; i++)
            acc = fmaf(qe[i], summary_w[(DV + i)*DS + tid], acc);
        g_sumq_tab[q*DS + tid] = acc;
    }
    if (tid == 0) {
        float d = alpha_b[0];
        for (int i = 0; i < DK; i++) d = fmaf(qe[i], alpha_w[i], d);
        g_alpha_tab[q] = (d > 20.f) ? d : log1pf(expf(d));
    }
    if (tid < 4) {
        float d = beta_b[tid];
        for (int i = 0; i < DK; i++) d = fmaf(qe[i], beta_w[i*4 + tid], d);
        g_beta_tab[q*4 + tid] = d;
    }
}

// ---------------- K2: per-(q,r) erase/add table, packed ----------------
__global__ void ertab_kernel(const float* __restrict__ item_embed_w)
{
    int q = blockIdx.x / KK;
    int r = blockIdx.x % KK;
    int j = threadIdx.x;                 // 128 threads
    __shared__ float it[DK];
    __shared__ float es[DV];
    __shared__ float as_[DV];
    if (j < DK) it[j] = item_embed_w[q*DK + j];
    __syncthreads();

    float rf[KK];
    #pragma unroll
    for (int k = 0; k < KK; k++) {
        float d = fabsf((float)k - (float)r) * 0.25f;
        rf[k] = fmaxf(1.f - d, 0.f);
    }
    float pe = g_b1e[j], pa = g_b1a[j];
    #pragma unroll 8
    for (int i = 0; i < DK; i++) {
        float x = it[i];
        pe = fmaf(x, g_W1e[i*DV + j], pe);
        pa = fmaf(x, g_W1a[i*DV + j], pa);
    }
    #pragma unroll
    for (int k = 0; k < KK; k++) {
        pe = fmaf(rf[k], g_W1e[(DK + k)*DV + j], pe);
        pa = fmaf(rf[k], g_W1a[(DK + k)*DV + j], pa);
    }
    es[j]  = 1.f / (1.f + expf(-pe));
    as_[j] = tanhf(pa);
    __syncthreads();

    if (j < 64) {
        int c = q*KK + r;
        g_ea[(size_t)c*128 + j*2]     = pack2(-es[2*j], -es[2*j+1]);
        g_ea[(size_t)c*128 + j*2 + 1] = pack2(as_[2*j], as_[2*j+1]);
    }
}

// ---------------- K3: scan — R7 structure + smem-staged ea ----------------
// grid = 512 = 128 batches x 4 v-slices; block = 64 thr (2 warps).
// tid = mh*16 + vpl; thread owns mem rows m = mh*13 .. mh*13+12 for v-pair vp.
// attn (52 u64) and ea (16 ulonglong2) staged per block-step into smem;
// double-buffered, ONE __syncthreads per step, depth-2 LDG prefetch so the
// STS never waits on an in-flight global load.
__global__ void __launch_bounds__(64, 8)
scan_kernel(const int* __restrict__ questions, const int* __restrict__ responses,
            const float* __restrict__ init_mem)
{
    const int tid = threadIdx.x;
    const int vpl = tid & 15;
    const int mh  = tid >> 4;                 // 0..3
    const int b   = blockIdx.x >> 2;
    const int vs  = blockIdx.x & 3;
    const int vp  = vs*16 + vpl;              // 0..63

    __shared__ __align__(16) u64 s_attn[2][64];        // groups of 16 (13 used)
    __shared__ __align__(16) ulonglong2 s_ea[2][16];   // per vpl: (ne, a)
    __shared__ u64 s_rd[2][3][16];

    u64 mem[13];
    #pragma unroll
    for (int j = 0; j < 13; j++) {
        int m = mh*13 + j;
        if (m < MM) {
            float2 iv = *(const float2*)(init_mem + m*DV + 2*vp);
            mem[j] = pack2(iv.x, iv.y);
        } else mem[j] = 0ULL;
    }

    const int base = b*SS;

    int q0 = questions[base + 0], r0 = responses[base + 0];
    int q1 = questions[base + 1], r1 = responses[base + 1];
    int q2 = questions[base + 2], r2 = responses[base + 2];

    // attn slot remap: m = g*13+i  ->  slot g*16+i  (aligned LDS.128 reads)
    const int slot = (tid/13)*16 + (tid - (tid/13)*13);
    u64 ap_n1 = 0ULL;
    ulonglong2 ea_n1 = make_ulonglong2(0ULL, 0ULL);
    if (tid < 52) {
        s_attn[0][slot] = g_attn2[q0*64 + tid];       // m>=50 slots zero in table
        ap_n1 = g_attn2[q1*64 + tid];
    }
    if (tid < 16) {
        s_ea[0][tid] = *(const ulonglong2*)(g_ea + ((size_t)(q0*KK + r0))*128 + (vs*16 + tid)*2);
        ea_n1        = *(const ulonglong2*)(g_ea + ((size_t)(q1*KK + r1))*128 + (vs*16 + tid)*2);
    }
    __syncthreads();

    float* rdout = g_read + (size_t)base*DV + 2*vp;

    for (int t = 0; t < SS; t++) {
        // depth-2 prefetch: tables for t+2, indices for t+3
        u64 ap_n2 = 0ULL;
        ulonglong2 ea_n2 = make_ulonglong2(0ULL, 0ULL);
        if (tid < 52) ap_n2 = g_attn2[q2*64 + tid];
        if (tid < 16)
            ea_n2 = *(const ulonglong2*)(g_ea + ((size_t)(q2*KK + r2))*128 + (vs*16 + tid)*2);
        int tn = (t + 3 < SS) ? (t + 3) : (SS - 1);
        int q3 = questions[base + tn], r3 = responses[base + tn];

        // stage tables for t+1 (registers landed a full iteration ago)
        if (tid < 52) s_attn[(t + 1) & 1][slot] = ap_n1;
        if (tid < 16) s_ea[(t + 1) & 1][tid] = ea_n1;

        // body: 13 m-rows x 3 packed FMAs; attn + ea via broadcast LDS
        const int buf = t & 1;
        const ulonglong2 E = s_ea[buf][vpl];
        const u64 ne = E.x, ad = E.y;
        const u64* at = &s_attn[buf][mh*16];
        u64 rd = 0ULL;
        #pragma unroll
        for (int jj = 0; jj < 6; jj++) {
            ulonglong2 T = *(const ulonglong2*)(at + 2*jj);
            u64 m0 = mem[2*jj], m1 = mem[2*jj + 1];
            rd = fma2(T.x, m0, rd);
            u64 t0 = fma2(ne, m0, ad);
            mem[2*jj] = fma2(T.x, t0, m0);
            rd = fma2(T.y, m1, rd);
            u64 t1 = fma2(ne, m1, ad);
            mem[2*jj + 1] = fma2(T.y, t1, m1);
        }
        {
            u64 T = at[12];
            rd = fma2(T, mem[12], rd);
            u64 t0 = fma2(ne, mem[12], ad);
            mem[12] = fma2(T, t0, mem[12]);
        }

        if (mh) s_rd[buf][mh - 1][vpl] = rd;
        __syncthreads();

        if (mh == 0) {
            float2 f  = unpack2(rd);
            float2 p0 = unpack2(s_rd[buf][0][vpl]);
            float2 p1 = unpack2(s_rd[buf][1][vpl]);
            float2 p2 = unpack2(s_rd[buf][2][vpl]);
            float2 o;
            o.x = (f.x + p0.x) + (p1.x + p2.x);
            o.y = (f.y + p0.y) + (p1.y + p2.y);
            *(float2*)(rdout + (size_t)t*DV) = o;
        }

        ap_n1 = ap_n2;
        ea_n1 = ea_n2;
        q2 = q3; r2 = r3;
    }
}

// ---------------- K4: epilogue — f32x2 GEMV, w in regs, 8-row groups ------
#define TB 32
#define RT 8
__global__ void __launch_bounds__(128)
out_kernel(const int* __restrict__ questions,
           const float* __restrict__ summary_w,
           const float* __restrict__ theta_w,
           const float* __restrict__ theta_b,
           float* __restrict__ out)
{
    const int tid  = threadIdx.x;
    const int s    = tid & 63;
    const int ih   = tid >> 6;
    const int lane = tid & 31;
    const int wid  = tid >> 5;

    __shared__ __align__(16) float s_read[RT][DV];
    __shared__ float s_part[RT][64];
    __shared__ float s_sum[RT][52];
    __shared__ int   s_q[RT];

    // register-cache w as packed pairs over the i-dimension
    const int sc = (s < DS) ? s : 0;
    u64 w2[32];
    #pragma unroll
    for (int j = 0; j < 32; j++)
        w2[j] = pack2(summary_w[(ih*64 + 2*j)*DS + sc],
                      summary_w[(ih*64 + 2*j + 1)*DS + sc]);

    float tw0 = 0.f, tw1 = 0.f;
    if (lane < 25) { tw0 = theta_w[2*lane]; tw1 = theta_w[2*lane + 1]; }
    const float tb0 = theta_b[0];

    #pragma unroll 1
    for (int tile = 0; tile < TB/RT; tile++) {
        const int bt0 = blockIdx.x * TB + tile * RT;

        if (tid < RT) s_q[tid] = questions[bt0 + tid];
        {
            float4* dst = (float4*)&s_read[0][0];
            const float4* src = (const float4*)(g_read + (size_t)bt0*DV);
            dst[tid]       = src[tid];
            dst[tid + 128] = src[tid + 128];
        }
        __syncthreads();

        float sumq[RT];
        if (!ih && s < DS) {
            #pragma unroll
            for (int r = 0; r < RT; r++) sumq[r] = g_sumq_tab[s_q[r]*DS + s];
        }

        float acc[RT];
        #pragma unroll
        for (int r = 0; r < RT; r++) {
            u64 a2 = 0ULL;
            const ulonglong2* r4 = (const ulonglong2*)(&s_read[r][ih*64]);
            #pragma unroll
            for (int j = 0; j < 16; j++) {
                ulonglong2 rv = r4[j];            // broadcast LDS.128 = 2 f32x2 pairs
                a2 = fma2(rv.x, w2[2*j],     a2);
                a2 = fma2(rv.y, w2[2*j + 1], a2);
            }
            float2 f = unpack2(a2);
            acc[r] = f.x + f.y;
        }
        if (ih) {
            #pragma unroll
            for (int r = 0; r < RT; r++) s_part[r][s] = acc[r];
        }
        __syncthreads();

        if (!ih && s < DS) {
            #pragma unroll
            for (int r = 0; r < RT; r++)
                s_sum[r][s] = tanhf(acc[r] + s_part[r][s] + sumq[r]);
        }
        __syncthreads();

        #pragma unroll
        for (int k = 0; k < 2; k++) {
            const int r  = wid*2 + k;
            const int bt = bt0 + r;
            const int q  = s_q[r];
            float p = (lane < 25) ? s_sum[r][2*lane]*tw0 + s_sum[r][2*lane+1]*tw1 : 0.f;
            p += __shfl_xor_sync(0xffffffffu, p, 16);
            p += __shfl_xor_sync(0xffffffffu, p, 8);
            p += __shfl_xor_sync(0xffffffffu, p, 4);
            p += __shfl_xor_sync(0xffffffffu, p, 2);
            p += __shfl_xor_sync(0xffffffffu, p, 1);
            if (lane == 0) {
                float th = tanhf(p + tb0);
                float al = g_alpha_tab[q];
                float inter = th * al;

                float l[5];
                l[0] = 0.f;
                #pragma unroll
                for (int cc = 0; cc < 4; cc++)
                    l[cc+1] = l[cc] + (inter - g_beta_tab[q*4 + cc]);

                float mx = l[0];
                #pragma unroll
                for (int cc = 1; cc < 5; cc++) mx = fmaxf(mx, l[cc]);
                float ex[5], sm = 0.f;
                #pragma unroll
                for (int cc = 0; cc < 5; cc++) { ex[cc] = __expf(l[cc] - mx); sm += ex[cc]; }
                float inv = 1.f / sm;

                out[bt]             = th;
                out[OFF_ALPHA + bt] = al;
                #pragma unroll
                for (int cc = 0; cc < 4; cc++) out[OFF_BETA + bt*4 + cc] = g_beta_tab[q*4 + cc];
                #pragma unroll
                for (int cc = 0; cc < 5; cc++) out[OFF_LOGITS + bt*5 + cc] = l[cc];
                #pragma unroll
                for (int cc = 0; cc < 5; cc++) out[OFF_PROBS  + bt*5 + cc] = ex[cc] * inv;
            }
        }
        __syncthreads();
    }
}

// ---------------- launch ----------------
extern "C" void kernel_launch(void* const* d_in, const int* in_sizes, int n_in,
                              void* d_out, int out_size)
{
    const int*   questions    = (const int*)  d_in[0];
    const int*   responses    = (const int*)  d_in[1];
    const float* q_embed_w    = (const float*)d_in[2];
    const float* item_embed_w = (const float*)d_in[3];
    const float* value_proj_w = (const float*)d_in[4];
    const float* value_proj_b = (const float*)d_in[5];
    const float* key_mem      = (const float*)d_in[6];
    const float* init_mem     = (const float*)d_in[7];
    const float* erase_w      = (const float*)d_in[8];
    const float* erase_b      = (const float*)d_in[9];
    const float* add_w        = (const float*)d_in[10];
    const float* add_b        = (const float*)d_in[11];
    const float* summary_w    = (const float*)d_in[12];
    const float* summary_b    = (const float*)d_in[13];
    const float* theta_w      = (const float*)d_in[14];
    const float* theta_b      = (const float*)d_in[15];
    const float* alpha_w      = (const float*)d_in[16];
    const float* alpha_b      = (const float*)d_in[17];
    const float* beta_w       = (const float*)d_in[18];
    const float* beta_b       = (const float*)d_in[19];
    float* out = (float*)d_out;

    fuse_kernel <<<70, DV>>>(value_proj_w, value_proj_b, erase_w, erase_b, add_w, add_b);
    qtab_kernel <<<NQ, 64>>>(q_embed_w, key_mem, summary_w, summary_b,
                             alpha_w, alpha_b, beta_w, beta_b);
    ertab_kernel<<<NQ*KK, DV>>>(item_embed_w);
    scan_kernel <<<BB*4, 64>>>(questions, responses, init_mem);
    out_kernel  <<<NBT/TB, 128>>>(questions, summary_w, theta_w, theta_b, out);
}

// round 12
// speedup vs baseline: 1.3238x; 1.0644x over previous
#include <cuda_runtime.h>
#include <math.h>

#define NQ   1001
#define KK   5
#define MM   50
#define DK   64
#define DV   128
#define DS   50
#define BB   128
#define SS   2048

#define NBT      (BB*SS)
#define OFF_ALPHA  (NBT)
#define OFF_BETA   (2*NBT)
#define OFF_LOGITS (2*NBT + NBT*4)
#define OFF_PROBS  (2*NBT + NBT*4 + NBT*5)

#define CH   8            // steps per chunk
#define NCH  (SS/CH)      // 256 chunks

typedef unsigned long long u64;

__device__ __forceinline__ u64 fma2(u64 a, u64 b, u64 c) {
    u64 d;
    asm("fma.rn.f32x2 %0, %1, %2, %3;" : "=l"(d) : "l"(a), "l"(b), "l"(c));
    return d;
}
__device__ __forceinline__ u64 add2(u64 a, u64 b) {
    u64 d;
    asm("add.rn.f32x2 %0, %1, %2;" : "=l"(d) : "l"(a), "l"(b));
    return d;
}
__device__ __forceinline__ u64 pack2(float x, float y) {
    u64 d;
    asm("mov.b64 %0, {%1, %2};" : "=l"(d) : "r"(__float_as_uint(x)), "r"(__float_as_uint(y)));
    return d;
}
__device__ __forceinline__ float2 unpack2(u64 v) {
    float2 f;
    asm("mov.b64 {%0, %1}, %2;" : "=f"(f.x), "=f"(f.y) : "l"(v));
    return f;
}

// ---------------- static scratch ----------------
__device__ float g_W1e[69*DV];
__device__ float g_b1e[DV];
__device__ float g_W1a[69*DV];
__device__ float g_b1a[DV];
__device__ __align__(16) u64 g_attn2[NQ*64];      // dup-packed, padded to 64 m-slots
__device__ __align__(16) u64 g_ea[NQ*KK*128];     // per vp: [2*vp]=(-e0,-e1) [2*vp+1]=(a0,a1)
__device__ float g_sumq_tab[NQ*DS];               // q_e @ summary_w[128:192,:] + summary_b
__device__ float g_alpha_tab[NQ];
__device__ float g_beta_tab[NQ*4];
__device__ float g_read[(size_t)NBT*DV];

// ---------------- K0: fuse value_proj through erase/add ----------
__global__ void fuse_kernel(const float* __restrict__ vp_w, const float* __restrict__ vp_b,
                            const float* __restrict__ er_w, const float* __restrict__ er_b,
                            const float* __restrict__ ad_w, const float* __restrict__ ad_b)
{
    int j = threadIdx.x;
    int row = blockIdx.x;
    if (row < 69) {
        float ae = 0.f, aa = 0.f;
        #pragma unroll 8
        for (int k = 0; k < DV; k++) {
            float w = vp_w[row*DV + k];
            ae = fmaf(w, er_w[k*DV + j], ae);
            aa = fmaf(w, ad_w[k*DV + j], aa);
        }
        g_W1e[row*DV + j] = ae;
        g_W1a[row*DV + j] = aa;
    } else {
        float be = er_b[j], ba = ad_b[j];
        #pragma unroll 8
        for (int k = 0; k < DV; k++) {
            float b = vp_b[k];
            be = fmaf(b, er_w[k*DV + j], be);
            ba = fmaf(b, ad_w[k*DV + j], ba);
        }
        g_b1e[j] = be;
        g_b1a[j] = ba;
    }
}

// ---------------- K1: per-question tables ----------------
__global__ void qtab_kernel(const float* __restrict__ q_embed_w,
                            const float* __restrict__ key_mem,
                            const float* __restrict__ summary_w,
                            const float* __restrict__ summary_b,
                            const float* __restrict__ alpha_w, const float* __restrict__ alpha_b,
                            const float* __restrict__ beta_w,  const float* __restrict__ beta_b)
{
    int q = blockIdx.x;
    int tid = threadIdx.x;               // 64 threads
    __shared__ float qe[DK];
    __shared__ float lg[MM];
    __shared__ float aw[64];
    qe[tid] = q_embed_w[q*DK + tid];
    __syncthreads();

    if (tid < MM) {
        float acc = 0.f;
        #pragma unroll 8
        for (int i = 0; i < DK; i++) acc = fmaf(qe[i], key_mem[tid*DK + i], acc);
        lg[tid] = acc;
    }
    __syncthreads();
    if (tid == 0) {
        float mx = lg[0];
        for (int m = 1; m < MM; m++) mx = fmaxf(mx, lg[m]);
        float s = 0.f;
        for (int m = 0; m < MM; m++) { float e = expf(lg[m] - mx); aw[m] = e; s += e; }
        float inv = 1.f / s;
        for (int m = 0; m < MM; m++) aw[m] *= inv;
        for (int m = MM; m < 64; m++) aw[m] = 0.f;
    }
    __syncthreads();
    {
        float v = aw[tid];
        g_attn2[q*64 + tid] = pack2(v, v);
    }

    if (tid < DS) {
        float acc = summary_b[tid];
        #pragma unroll 8
        for (int i = 0; i < DK; i++)
            acc = fmaf(qe[i], summary_w[(DV + i)*DS + tid], acc);
        g_sumq_tab[q*DS + tid] = acc;
    }
    if (tid == 0) {
        float d = alpha_b[0];
        for (int i = 0; i < DK; i++) d = fmaf(qe[i], alpha_w[i], d);
        g_alpha_tab[q] = (d > 20.f) ? d : log1pf(expf(d));
    }
    if (tid < 4) {
        float d = beta_b[tid];
        for (int i = 0; i < DK; i++) d = fmaf(qe[i], beta_w[i*4 + tid], d);
        g_beta_tab[q*4 + tid] = d;
    }
}

// ---------------- K2: per-(q,r) erase/add table, packed ----------------
__global__ void ertab_kernel(const float* __restrict__ item_embed_w)
{
    int q = blockIdx.x / KK;
    int r = blockIdx.x % KK;
    int j = threadIdx.x;                 // 128 threads
    __shared__ float it[DK];
    __shared__ float es[DV];
    __shared__ float as_[DV];
    if (j < DK) it[j] = item_embed_w[q*DK + j];
    __syncthreads();

    float rf[KK];
    #pragma unroll
    for (int k = 0; k < KK; k++) {
        float d = fabsf((float)k - (float)r) * 0.25f;
        rf[k] = fmaxf(1.f - d, 0.f);
    }
    float pe = g_b1e[j], pa = g_b1a[j];
    #pragma unroll 8
    for (int i = 0; i < DK; i++) {
        float x = it[i];
        pe = fmaf(x, g_W1e[i*DV + j], pe);
        pa = fmaf(x, g_W1a[i*DV + j], pa);
    }
    #pragma unroll
    for (int k = 0; k < KK; k++) {
        pe = fmaf(rf[k], g_W1e[(DK + k)*DV + j], pe);
        pa = fmaf(rf[k], g_W1a[(DK + k)*DV + j], pa);
    }
    es[j]  = 1.f / (1.f + expf(-pe));
    as_[j] = tanhf(pa);
    __syncthreads();

    if (j < 64) {
        int c = q*KK + r;
        g_ea[(size_t)c*128 + j*2]     = pack2(-es[2*j], -es[2*j+1]);
        g_ea[(size_t)c*128 + j*2 + 1] = pack2(as_[2*j], as_[2*j+1]);
    }
}

// ---------------- K3: scan — chunked, ONE barrier per 8 steps -------------
// grid = 512 = 128 batches x 4 v-slices; block = 64 thr (2 warps).
// tid = mh*16 + vpl; thread owns mem rows m = mh*13 .. mh*13+12 for v-pair vp.
// Tables for CH=8 steps staged per chunk into TRIPLE-buffered smem (the STS
// for chunk k+1 happens before barrier k, while chunk k-1's readers may still
// be in flight — 3 buffers break the WAR race). Read-partials are written
// per-step with NO sync (g_read doesn't feed the recurrence) and reduced
// lazily one chunk later from a double-buffered s_rd.
__global__ void __launch_bounds__(64, 8)
scan_kernel(const int* __restrict__ questions, const int* __restrict__ responses,
            const float* __restrict__ init_mem)
{
    const int tid = threadIdx.x;
    const int vpl = tid & 15;
    const int mh  = tid >> 4;                 // 0..3
    const int b   = blockIdx.x >> 2;
    const int vs  = blockIdx.x & 3;
    const int vp  = vs*16 + vpl;              // 0..63

    __shared__ __align__(16) u64 s_attn[3][CH][64];       // 12 KB
    __shared__ __align__(16) ulonglong2 s_ea[3][CH][16];  // 6 KB
    __shared__ __align__(16) u64 s_rd[2][CH][16][4];      // 8 KB  [vpl][mh]

    u64 mem[13];
    #pragma unroll
    for (int j = 0; j < 13; j++) {
        int m = mh*13 + j;
        if (m < MM) {
            float2 iv = *(const float2*)(init_mem + m*DV + 2*vp);
            mem[j] = pack2(iv.x, iv.y);
        } else mem[j] = 0ULL;
    }

    const int base = b*SS;
    const bool is_at = (tid < 52);            // attn stagers
    const bool is_ea = (tid >= 48);           // ea stagers (slot = tid-48)
    const int  eslot = tid - 48;
    // attn slot remap: m = g*13+i -> slot g*16+i (aligned LDS.128 reads)
    const int slot = (tid/13)*16 + (tid - (tid/13)*13);

    // ---- prologue ----
    // chunk 0 -> smem buf 0
    {
        #pragma unroll
        for (int i = 0; i < CH; i++) {
            int qq = questions[base + i];
            int cc = qq*KK + responses[base + i];
            if (is_at) s_attn[0][i][slot] = g_attn2[qq*64 + tid];
            if (is_ea) s_ea[0][i][eslot] =
                *(const ulonglong2*)(g_ea + (size_t)cc*128 + (vs*16 + eslot)*2);
        }
    }
    // chunk 1 -> registers
    u64 apA[CH];
    ulonglong2 eaA[CH];
    {
        #pragma unroll
        for (int i = 0; i < CH; i++) {
            int qq = questions[base + CH + i];
            int cc = qq*KK + responses[base + CH + i];
            apA[i] = is_at ? g_attn2[qq*64 + tid] : 0ULL;
            eaA[i] = is_ea ? *(const ulonglong2*)(g_ea + (size_t)cc*128 + (vs*16 + eslot)*2)
                           : make_ulonglong2(0ULL, 0ULL);
        }
    }
    // chunk 2 indices -> registers
    int qn[CH], cn[CH];
    #pragma unroll
    for (int i = 0; i < CH; i++) {
        qn[i] = questions[base + 2*CH + i];
        cn[i] = qn[i]*KK + responses[base + 2*CH + i];
    }
    __syncthreads();

    float* rdout = g_read + (size_t)base*DV + 2*vp;

    int buf3 = 0;                              // chunk k's table buffer (mod 3)
    #pragma unroll 1
    for (int k = 0; k < NCH; k++) {
        const int nbuf3 = (buf3 == 2) ? 0 : buf3 + 1;
        // 1. STS tables for chunk k+1 (registers landed during chunk k-1)
        if (is_at) {
            #pragma unroll
            for (int i = 0; i < CH; i++) s_attn[nbuf3][i][slot] = apA[i];
        }
        if (is_ea) {
            #pragma unroll
            for (int i = 0; i < CH; i++) s_ea[nbuf3][i][eslot] = eaA[i];
        }
        // 2. LDG tables for chunk k+2
        if (is_at) {
            #pragma unroll
            for (int i = 0; i < CH; i++) apA[i] = g_attn2[qn[i]*64 + tid];
        }
        if (is_ea) {
            #pragma unroll
            for (int i = 0; i < CH; i++)
                eaA[i] = *(const ulonglong2*)(g_ea + (size_t)cn[i]*128 + (vs*16 + eslot)*2);
        }
        // 3. indices for chunk k+3
        {
            int nk = (k + 3 < NCH) ? k + 3 : NCH - 1;
            #pragma unroll
            for (int i = 0; i < CH; i++) {
                qn[i] = questions[base + nk*CH + i];
                cn[i] = qn[i]*KK + responses[base + nk*CH + i];
            }
        }
        // 4. single barrier: publishes buf for k+1, makes chunk k-1 partials visible
        __syncthreads();

        // 5. lazy reduction of chunk k-1 partials (mh==0 threads)
        if (mh == 0 && k > 0) {
            const int pb = (k - 1) & 1;
            #pragma unroll
            for (int i = 0; i < CH; i++) {
                const ulonglong2* p = (const ulonglong2*)(&s_rd[pb][i][vpl][0]);
                ulonglong2 a0 = p[0], a1 = p[1];
                u64 s01 = add2(a0.x, a0.y);
                u64 s23 = add2(a1.x, a1.y);
                *(u64*)(rdout + (size_t)((k - 1)*CH + i)*DV) = add2(s01, s23);
            }
        }

        // 6. 8-step body — no syncs, recurrence register-local
        const int wb = k & 1;
        #pragma unroll
        for (int i = 0; i < CH; i++) {
            const ulonglong2 E = s_ea[buf3][i][vpl];
            const u64 ne = E.x, ad = E.y;
            const u64* at = &s_attn[buf3][i][mh*16];
            u64 rd = 0ULL;
            #pragma unroll
            for (int jj = 0; jj < 6; jj++) {
                ulonglong2 T = *(const ulonglong2*)(at + 2*jj);
                u64 m0 = mem[2*jj], m1 = mem[2*jj + 1];
                rd = fma2(T.x, m0, rd);
                u64 t0 = fma2(ne, m0, ad);
                mem[2*jj] = fma2(T.x, t0, m0);
                rd = fma2(T.y, m1, rd);
                u64 t1 = fma2(ne, m1, ad);
                mem[2*jj + 1] = fma2(T.y, t1, m1);
            }
            {
                u64 T = at[12];
                rd = fma2(T, mem[12], rd);
                u64 t0 = fma2(ne, mem[12], ad);
                mem[12] = fma2(T, t0, mem[12]);
            }
            s_rd[wb][i][vpl][mh] = rd;
        }

        buf3 = nbuf3;
    }

    // epilogue: reduce the final chunk's partials
    __syncthreads();
    if (mh == 0) {
        const int pb = (NCH - 1) & 1;
        #pragma unroll
        for (int i = 0; i < CH; i++) {
            const ulonglong2* p = (const ulonglong2*)(&s_rd[pb][i][vpl][0]);
            ulonglong2 a0 = p[0], a1 = p[1];
            u64 s01 = add2(a0.x, a0.y);
            u64 s23 = add2(a1.x, a1.y);
            *(u64*)(rdout + (size_t)((NCH - 1)*CH + i)*DV) = add2(s01, s23);
        }
    }
}

// ---------------- K4: epilogue — f32x2 GEMV, w in regs, 8-row groups ------
#define TB 32
#define RT 8
__global__ void __launch_bounds__(128)
out_kernel(const int* __restrict__ questions,
           const float* __restrict__ summary_w,
           const float* __restrict__ theta_w,
           const float* __restrict__ theta_b,
           float* __restrict__ out)
{
    const int tid  = threadIdx.x;
    const int s    = tid & 63;
    const int ih   = tid >> 6;
    const int lane = tid & 31;
    const int wid  = tid >> 5;

    __shared__ __align__(16) float s_read[RT][DV];
    __shared__ float s_part[RT][64];
    __shared__ float s_sum[RT][52];
    __shared__ int   s_q[RT];

    const int sc = (s < DS) ? s : 0;
    u64 w2[32];
    #pragma unroll
    for (int j = 0; j < 32; j++)
        w2[j] = pack2(summary_w[(ih*64 + 2*j)*DS + sc],
                      summary_w[(ih*64 + 2*j + 1)*DS + sc]);

    float tw0 = 0.f, tw1 = 0.f;
    if (lane < 25) { tw0 = theta_w[2*lane]; tw1 = theta_w[2*lane + 1]; }
    const float tb0 = theta_b[0];

    #pragma unroll 1
    for (int tile = 0; tile < TB/RT; tile++) {
        const int bt0 = blockIdx.x * TB + tile * RT;

        if (tid < RT) s_q[tid] = questions[bt0 + tid];
        {
            float4* dst = (float4*)&s_read[0][0];
            const float4* src = (const float4*)(g_read + (size_t)bt0*DV);
            dst[tid]       = src[tid];
            dst[tid + 128] = src[tid + 128];
        }
        __syncthreads();

        float sumq[RT];
        if (!ih && s < DS) {
            #pragma unroll
            for (int r = 0; r < RT; r++) sumq[r] = g_sumq_tab[s_q[r]*DS + s];
        }

        float acc[RT];
        #pragma unroll
        for (int r = 0; r < RT; r++) {
            u64 a2 = 0ULL;
            const ulonglong2* r4 = (const ulonglong2*)(&s_read[r][ih*64]);
            #pragma unroll
            for (int j = 0; j < 16; j++) {
                ulonglong2 rv = r4[j];
                a2 = fma2(rv.x, w2[2*j],     a2);
                a2 = fma2(rv.y, w2[2*j + 1], a2);
            }
            float2 f = unpack2(a2);
            acc[r] = f.x + f.y;
        }
        if (ih) {
            #pragma unroll
            for (int r = 0; r < RT; r++) s_part[r][s] = acc[r];
        }
        __syncthreads();

        if (!ih && s < DS) {
            #pragma unroll
            for (int r = 0; r < RT; r++)
                s_sum[r][s] = tanhf(acc[r] + s_part[r][s] + sumq[r]);
        }
        __syncthreads();

        #pragma unroll
        for (int k = 0; k < 2; k++) {
            const int r  = wid*2 + k;
            const int bt = bt0 + r;
            const int q  = s_q[r];
            float p = (lane < 25) ? s_sum[r][2*lane]*tw0 + s_sum[r][2*lane+1]*tw1 : 0.f;
            p += __shfl_xor_sync(0xffffffffu, p, 16);
            p += __shfl_xor_sync(0xffffffffu, p, 8);
            p += __shfl_xor_sync(0xffffffffu, p, 4);
            p += __shfl_xor_sync(0xffffffffu, p, 2);
            p += __shfl_xor_sync(0xffffffffu, p, 1);
            if (lane == 0) {
                float th = tanhf(p + tb0);
                float al = g_alpha_tab[q];
                float inter = th * al;

                float l[5];
                l[0] = 0.f;
                #pragma unroll
                for (int cc = 0; cc < 4; cc++)
                    l[cc+1] = l[cc] + (inter - g_beta_tab[q*4 + cc]);

                float mx = l[0];
                #pragma unroll
                for (int cc = 1; cc < 5; cc++) mx = fmaxf(mx, l[cc]);
                float ex[5], sm = 0.f;
                #pragma unroll
                for (int cc = 0; cc < 5; cc++) { ex[cc] = __expf(l[cc] - mx); sm += ex[cc]; }
                float inv = 1.f / sm;

                out[bt]             = th;
                out[OFF_ALPHA + bt] = al;
                #pragma unroll
                for (int cc = 0; cc < 4; cc++) out[OFF_BETA + bt*4 + cc] = g_beta_tab[q*4 + cc];
                #pragma unroll
                for (int cc = 0; cc < 5; cc++) out[OFF_LOGITS + bt*5 + cc] = l[cc];
                #pragma unroll
                for (int cc = 0; cc < 5; cc++) out[OFF_PROBS  + bt*5 + cc] = ex[cc] * inv;
            }
        }
        __syncthreads();
    }
}

// ---------------- launch ----------------
extern "C" void kernel_launch(void* const* d_in, const int* in_sizes, int n_in,
                              void* d_out, int out_size)
{
    const int*   questions    = (const int*)  d_in[0];
    const int*   responses    = (const int*)  d_in[1];
    const float* q_embed_w    = (const float*)d_in[2];
    const float* item_embed_w = (const float*)d_in[3];
    const float* value_proj_w = (const float*)d_in[4];
    const float* value_proj_b = (const float*)d_in[5];
    const float* key_mem      = (const float*)d_in[6];
    const float* init_mem     = (const float*)d_in[7];
    const float* erase_w      = (const float*)d_in[8];
    const float* erase_b      = (const float*)d_in[9];
    const float* add_w        = (const float*)d_in[10];
    const float* add_b        = (const float*)d_in[11];
    const float* summary_w    = (const float*)d_in[12];
    const float* summary_b    = (const float*)d_in[13];
    const float* theta_w      = (const float*)d_in[14];
    const float* theta_b      = (const float*)d_in[15];
    const float* alpha_w      = (const float*)d_in[16];
    const float* alpha_b      = (const float*)d_in[17];
    const float* beta_w       = (const float*)d_in[18];
    const float* beta_b       = (const float*)d_in[19];
    float* out = (float*)d_out;

    fuse_kernel <<<70, DV>>>(value_proj_w, value_proj_b, erase_w, erase_b, add_w, add_b);
    qtab_kernel <<<NQ, 64>>>(q_embed_w, key_mem, summary_w, summary_b,
                             alpha_w, alpha_b, beta_w, beta_b);
    ertab_kernel<<<NQ*KK, DV>>>(item_embed_w);
    scan_kernel <<<BB*4, 64>>>(questions, responses, init_mem);
    out_kernel  <<<NBT/TB, 128>>>(questions, summary_w, theta_w, theta_b, out);
}